// round 1
// baseline (speedup 1.0000x reference)
#include <cuda_runtime.h>

// memoryClusterer: superpixel gather + per-class contrast maps.
//   inputs (metadata order, per reference signature):
//     d_in[0] spx       int32  [1,1,1080,1920]
//     d_in[1] knn_pred  int32  [2000]
//     d_in[2] knn_dist  f32    [2000, 8]
//     d_in[3] cent_dist f32    [2000, 8]
//   output (float32, concatenated flattened tuple):
//     [0 .. HW)                      preseg  (knn_pred gathered, cast to float)
//     [HW .. HW + 7*4*HW)            attmaps [7, 4, H, W]
//        plane (a,k): a in 0..6 (class label j = a+1), k: 0=knn_att[j],
//        1=knn_contrast, 2=cent_att[j], 3=cent_contrast
//
// contrast_j = max over channels != j = (argmax==j ? max2 : max1).

static constexpr int Hh = 1080;
static constexpr int Ww = 1920;
static constexpr int HW = Hh * Ww;          // 2,073,600 (divisible by 4)
static constexpr int NC = 8;

__device__ __forceinline__ void load_row8(float v[NC], const float4* __restrict__ tab, int idx) {
    float4 a = __ldg(tab + idx * 2);
    float4 b = __ldg(tab + idx * 2 + 1);
    v[0] = a.x; v[1] = a.y; v[2] = a.z; v[3] = a.w;
    v[4] = b.x; v[5] = b.y; v[6] = b.z; v[7] = b.w;
}

__device__ __forceinline__ void max2of8(const float v[NC], float& m1, float& m2, int& arg) {
    m1 = v[0];
    m2 = __int_as_float(0xff800000);  // -inf
    arg = 0;
#pragma unroll
    for (int c = 1; c < NC; c++) {
        float x = v[c];
        if (x > m1) { m2 = m1; m1 = x; arg = c; }
        else if (x > m2) { m2 = x; }
    }
}

__global__ __launch_bounds__(256)
void memory_clusterer_kernel(const int4* __restrict__ spx4,
                             const int* __restrict__ knn_pred,
                             const float4* __restrict__ knn_dist4,
                             const float4* __restrict__ cent_dist4,
                             float* __restrict__ out) {
    int t = blockIdx.x * blockDim.x + threadIdx.x;
    int i = t << 2;                        // first pixel of this thread's group of 4
    if (i >= HW) return;

    int4 sp = __ldg(spx4 + t);
    int idx0 = sp.x - 1;
    int idx1 = sp.y - 1;
    int idx2 = sp.z - 1;
    int idx3 = sp.w - 1;

    // ---- preseg ----
    float4 pre;
    pre.x = (float)__ldg(knn_pred + idx0);
    pre.y = (float)__ldg(knn_pred + idx1);
    pre.z = (float)__ldg(knn_pred + idx2);
    pre.w = (float)__ldg(knn_pred + idx3);
    *reinterpret_cast<float4*>(out + i) = pre;

    float* base = out + HW + i;

    // ---- phase 1: knn table (planes k=0,1) ----
    {
        float v0[NC], v1[NC], v2[NC], v3[NC];
        load_row8(v0, knn_dist4, idx0);
        load_row8(v1, knn_dist4, idx1);
        load_row8(v2, knn_dist4, idx2);
        load_row8(v3, knn_dist4, idx3);

        float m1a, m2a, m1b, m2b, m1c, m2c, m1d, m2d;
        int aga, agb, agc, agd;
        max2of8(v0, m1a, m2a, aga);
        max2of8(v1, m1b, m2b, agb);
        max2of8(v2, m1c, m2c, agc);
        max2of8(v3, m1d, m2d, agd);

#pragma unroll
        for (int a = 0; a < 7; a++) {
            int j = a + 1;
            float4 att = make_float4(v0[j], v1[j], v2[j], v3[j]);
            *reinterpret_cast<float4*>(base + (size_t)(a * 4 + 0) * HW) = att;
            float4 con = make_float4(aga == j ? m2a : m1a,
                                     agb == j ? m2b : m1b,
                                     agc == j ? m2c : m1c,
                                     agd == j ? m2d : m1d);
            *reinterpret_cast<float4*>(base + (size_t)(a * 4 + 1) * HW) = con;
        }
    }

    // ---- phase 2: cent table (planes k=2,3) ----
    {
        float v0[NC], v1[NC], v2[NC], v3[NC];
        load_row8(v0, cent_dist4, idx0);
        load_row8(v1, cent_dist4, idx1);
        load_row8(v2, cent_dist4, idx2);
        load_row8(v3, cent_dist4, idx3);

        float m1a, m2a, m1b, m2b, m1c, m2c, m1d, m2d;
        int aga, agb, agc, agd;
        max2of8(v0, m1a, m2a, aga);
        max2of8(v1, m1b, m2b, agb);
        max2of8(v2, m1c, m2c, agc);
        max2of8(v3, m1d, m2d, agd);

#pragma unroll
        for (int a = 0; a < 7; a++) {
            int j = a + 1;
            float4 att = make_float4(v0[j], v1[j], v2[j], v3[j]);
            *reinterpret_cast<float4*>(base + (size_t)(a * 4 + 2) * HW) = att;
            float4 con = make_float4(aga == j ? m2a : m1a,
                                     agb == j ? m2b : m1b,
                                     agc == j ? m2c : m1c,
                                     agd == j ? m2d : m1d);
            *reinterpret_cast<float4*>(base + (size_t)(a * 4 + 3) * HW) = con;
        }
    }
}

extern "C" void kernel_launch(void* const* d_in, const int* in_sizes, int n_in,
                              void* d_out, int out_size) {
    const int4* spx4 = (const int4*)d_in[0];
    const int* knn_pred = (const int*)d_in[1];
    const float4* knn_dist4 = (const float4*)d_in[2];
    const float4* cent_dist4 = (const float4*)d_in[3];
    float* out = (float*)d_out;

    const int n_threads = HW / 4;          // 518,400
    const int block = 256;
    const int grid = (n_threads + block - 1) / block;  // 2025
    memory_clusterer_kernel<<<grid, block>>>(spx4, knn_pred, knn_dist4, cent_dist4, out);
}

// round 2
// speedup vs baseline: 1.0730x; 1.0730x over previous
#include <cuda_runtime.h>

// memoryClusterer: superpixel gather + per-class contrast maps.
//   d_in[0] spx       int32 [1,1,1080,1920]
//   d_in[1] knn_pred  int32 [2000]
//   d_in[2] knn_dist  f32   [2000,8]
//   d_in[3] cent_dist f32   [2000,8]
//   out (f32): [preseg (HW)] ++ [attmaps (7,4,H,W)]
//     plane (a,k): a=0..6 (class j=a+1); k: 0=knn_att[j], 1=knn_contrast,
//                                        2=cent_att[j], 3=cent_contrast
// contrast_j = max over channels != j = (argmax==j ? max2 : max1).
//
// R2: 1 pixel/thread (regs 80 -> ~34) to raise occupancy; gathers are
// latency-exposed at occ=33%. Store pattern stays fully coalesced
// (STG.32, 1 line/warp/instruction).

static constexpr int HW = 1080 * 1920;   // 2,073,600 = 8100 * 256
static constexpr int NC = 8;

__device__ __forceinline__ void max2of8(const float v[NC], float& m1, float& m2, int& arg) {
    m1 = v[0];
    m2 = __int_as_float(0xff800000);  // -inf
    arg = 0;
#pragma unroll
    for (int c = 1; c < NC; c++) {
        float x = v[c];
        if (x > m1) { m2 = m1; m1 = x; arg = c; }
        else if (x > m2) { m2 = x; }
    }
}

__global__ __launch_bounds__(256)
void memory_clusterer_kernel(const int* __restrict__ spx,
                             const int* __restrict__ knn_pred,
                             const float4* __restrict__ knn_dist4,
                             const float4* __restrict__ cent_dist4,
                             float* __restrict__ out) {
    const int i = blockIdx.x * blockDim.x + threadIdx.x;   // grid sized exactly

    const int idx = __ldg(spx + i) - 1;

    // Issue all 4 table loads + pred up-front for MLP.
    const float4 ka = __ldg(knn_dist4 + idx * 2);
    const float4 kb = __ldg(knn_dist4 + idx * 2 + 1);
    const float4 ca = __ldg(cent_dist4 + idx * 2);
    const float4 cb = __ldg(cent_dist4 + idx * 2 + 1);
    const int pred = __ldg(knn_pred + idx);

    out[i] = (float)pred;

    float* base = out + HW + i;

    // ---- knn planes (k = 0,1) ----
    {
        float v[NC] = {ka.x, ka.y, ka.z, ka.w, kb.x, kb.y, kb.z, kb.w};
        float m1, m2; int arg;
        max2of8(v, m1, m2, arg);
#pragma unroll
        for (int a = 0; a < 7; a++) {
            const int j = a + 1;
            base[(size_t)(a * 4 + 0) * HW] = v[j];
            base[(size_t)(a * 4 + 1) * HW] = (arg == j) ? m2 : m1;
        }
    }

    // ---- cent planes (k = 2,3) ----
    {
        float v[NC] = {ca.x, ca.y, ca.z, ca.w, cb.x, cb.y, cb.z, cb.w};
        float m1, m2; int arg;
        max2of8(v, m1, m2, arg);
#pragma unroll
        for (int a = 0; a < 7; a++) {
            const int j = a + 1;
            base[(size_t)(a * 4 + 2) * HW] = v[j];
            base[(size_t)(a * 4 + 3) * HW] = (arg == j) ? m2 : m1;
        }
    }
}

extern "C" void kernel_launch(void* const* d_in, const int* in_sizes, int n_in,
                              void* d_out, int out_size) {
    const int* spx = (const int*)d_in[0];
    const int* knn_pred = (const int*)d_in[1];
    const float4* knn_dist4 = (const float4*)d_in[2];
    const float4* cent_dist4 = (const float4*)d_in[3];
    float* out = (float*)d_out;

    const int block = 256;
    const int grid = HW / block;   // 8100, exact
    memory_clusterer_kernel<<<grid, block>>>(spx, knn_pred, knn_dist4, cent_dist4, out);
}